// round 2
// baseline (speedup 1.0000x reference)
#include <cuda_runtime.h>
#include <cuda_bf16.h>

// Problem shapes (fixed by the reference):
//   hidden          [1, B, H]  = [1, 32, 1024]   f32   d_in[0]
//   encoder_outputs [S, B, H]  = [2048, 32, 1024] f32  d_in[1]
//   W               [H, H]     = [1024, 1024]    f32   d_in[2]
//   b               [H]        = [1024]          f32   d_in[3]
//   out             [B, 1, S]  = [32, 1, 2048]   f32
//
// Math:
//   energies[b,s] = sum_h enc[s,b,h] * v[b,h] + hidden[b].bias
//   where v[b,h] = sum_o hidden[b,o] * W[o,h]
//   The bias term is constant over s -> drops out of softmax exactly.

#define S_DIM 2048
#define B_DIM 32
#define H_DIM 1024

// Scratch (allocation-free rule: __device__ globals)
__device__ float g_v[B_DIM * H_DIM];      // 128 KB
__device__ float g_e[B_DIM * S_DIM];      // 256 KB

// ---------------------------------------------------------------------------
// Kernel 0: zero the v accumulator (graph replays re-run everything)
// ---------------------------------------------------------------------------
__global__ void zero_v_kernel() {
    int i = blockIdx.x * blockDim.x + threadIdx.x;
    if (i < B_DIM * H_DIM) g_v[i] = 0.0f;
}

// ---------------------------------------------------------------------------
// Kernel 1: v[b,h] = sum_o hidden[b,o] * W[o,h]
// Grid: (H/128 = 8) x (o_splits = 16). Block: 128 threads (one h column each).
// Each block handles an o-chunk of 64; hidden[32][64] staged in shared;
// W read exactly once (coalesced over h). Epilogue: atomicAdd into g_v.
// ---------------------------------------------------------------------------
__global__ __launch_bounds__(128) void gemv_kernel(const float* __restrict__ hidden,
                                                   const float* __restrict__ W) {
    __shared__ float sh_hid[32 * 64];  // [b][oo]

    const int h  = blockIdx.x * 128 + threadIdx.x;
    const int o0 = blockIdx.y * 64;

    // Cooperative stage of hidden[0..31][o0..o0+63]
    #pragma unroll
    for (int k = 0; k < 16; ++k) {
        int idx = threadIdx.x + k * 128;          // 0..2047
        int b   = idx >> 6;                       // /64
        int oo  = idx & 63;
        sh_hid[idx] = hidden[b * H_DIM + o0 + oo];
    }
    __syncthreads();

    float acc[32];
    #pragma unroll
    for (int b = 0; b < 32; ++b) acc[b] = 0.0f;

    const float* Wp = W + (size_t)o0 * H_DIM + h;
    for (int oo = 0; oo < 64; ++oo) {
        float w = Wp[(size_t)oo * H_DIM];         // coalesced across threads (h)
        #pragma unroll
        for (int b = 0; b < 32; ++b)
            acc[b] += sh_hid[b * 64 + oo] * w;    // smem broadcast
    }

    #pragma unroll
    for (int b = 0; b < 32; ++b)
        atomicAdd(&g_v[b * H_DIM + h], acc[b]);   // coalesced RED over h
}

// ---------------------------------------------------------------------------
// Kernel 2 (the memory-bound one): energies[b,s] = dot(enc[s,b,:], v[b,:])
// Grid: (S/16, B). Block: 512 threads = 16 warps, one s-row per warp.
// v[b] staged in 4 KB shared. float4 loads, 8 independent LDG.128 per lane.
// ---------------------------------------------------------------------------
__global__ __launch_bounds__(512) void energy_kernel(const float* __restrict__ enc) {
    __shared__ float4 v_sh[H_DIM / 4];            // 4 KB

    const int b = blockIdx.y;

    // Stage v[b][:] : 256 float4 (first 256 threads)
    if (threadIdx.x < 256)
        v_sh[threadIdx.x] = ((const float4*)(g_v + b * H_DIM))[threadIdx.x];
    __syncthreads();

    const int warp = threadIdx.x >> 5;
    const int lane = threadIdx.x & 31;
    const int s    = blockIdx.x * 16 + warp;

    const float4* row = (const float4*)(enc + ((size_t)s * B_DIM + b) * H_DIM);

    float acc = 0.0f;
    #pragma unroll
    for (int i = 0; i < 8; ++i) {
        float4 e = row[lane + 32 * i];            // coalesced, MLP=8
        float4 v = v_sh[lane + 32 * i];
        acc += e.x * v.x + e.y * v.y + e.z * v.z + e.w * v.w;
    }

    // Warp reduction
    #pragma unroll
    for (int off = 16; off > 0; off >>= 1)
        acc += __shfl_xor_sync(0xFFFFFFFFu, acc, off);

    if (lane == 0) g_e[b * S_DIM + s] = acc;
}

// ---------------------------------------------------------------------------
// Kernel 3: softmax over s per batch; write out[b,0,s]
// One block (1024 threads) per b; each thread owns 2 s-positions.
// ---------------------------------------------------------------------------
__global__ __launch_bounds__(1024) void softmax_kernel(float* __restrict__ out) {
    __shared__ float red[32];

    const int b = blockIdx.x;
    const int t = threadIdx.x;
    const float* e = g_e + b * S_DIM;

    float e0 = e[t];
    float e1 = e[t + 1024];

    // --- block max ---
    float m = fmaxf(e0, e1);
    #pragma unroll
    for (int off = 16; off > 0; off >>= 1)
        m = fmaxf(m, __shfl_xor_sync(0xFFFFFFFFu, m, off));
    if ((t & 31) == 0) red[t >> 5] = m;
    __syncthreads();
    if (t < 32) {
        float v = red[t];
        #pragma unroll
        for (int off = 16; off > 0; off >>= 1)
            v = fmaxf(v, __shfl_xor_sync(0xFFFFFFFFu, v, off));
        red[t] = v;
    }
    __syncthreads();
    m = red[0];
    __syncthreads();

    // --- exp + block sum ---
    float x0 = expf(e0 - m);
    float x1 = expf(e1 - m);
    float s = x0 + x1;
    #pragma unroll
    for (int off = 16; off > 0; off >>= 1)
        s += __shfl_xor_sync(0xFFFFFFFFu, s, off);
    if ((t & 31) == 0) red[t >> 5] = s;
    __syncthreads();
    if (t < 32) {
        float v = red[t];
        #pragma unroll
        for (int off = 16; off > 0; off >>= 1)
            v += __shfl_xor_sync(0xFFFFFFFFu, v, off);
        red[t] = v;
    }
    __syncthreads();
    s = red[0];

    float inv = 1.0f / s;
    out[b * S_DIM + t]        = x0 * inv;
    out[b * S_DIM + t + 1024] = x1 * inv;
}

// ---------------------------------------------------------------------------
extern "C" void kernel_launch(void* const* d_in, const int* in_sizes, int n_in,
                              void* d_out, int out_size) {
    const float* hidden = (const float*)d_in[0];
    const float* enc    = (const float*)d_in[1];
    const float* W      = (const float*)d_in[2];
    // d_in[3] = bias: mathematically drops out of softmax (constant per b).

    float* out = (float*)d_out;

    zero_v_kernel<<<(B_DIM * H_DIM + 255) / 256, 256>>>();
    {
        dim3 grid(H_DIM / 128, 16);
        gemv_kernel<<<grid, 128>>>(hidden, W);
    }
    {
        dim3 grid(S_DIM / 16, B_DIM);
        energy_kernel<<<grid, 512>>>(enc);
    }
    softmax_kernel<<<B_DIM, 1024>>>(out);
}

// round 3
// speedup vs baseline: 1.5583x; 1.5583x over previous
#include <cuda_runtime.h>
#include <cuda_bf16.h>

// Shapes: hidden [1,32,1024] f32, enc [2048,32,1024] f32, W [1024,1024] f32,
//         bias [1024] f32 (drops out of softmax), out [32,1,2048] f32.
// energies[b,s] = dot(enc[s,b,:], v[b,:]),  v[b,h] = sum_o hidden[b,o] W[o,h]

#define S_DIM 2048
#define B_DIM 32
#define H_DIM 1024

__device__ float g_v[B_DIM * H_DIM];      // 128 KB scratch
__device__ float g_e[B_DIM * S_DIM];      // 256 KB scratch

// ---------------------------------------------------------------------------
// Kernel 1: v[b,h] = sum_o hidden[b,o] * W[o,h]
// Grid (H/128=8, o_splits=32), block 128. o-chunk of 32 per block.
// W loads batched 8-deep (MLP=8); epilogue coalesced atomicAdd (REDG).
// ---------------------------------------------------------------------------
__global__ __launch_bounds__(128) void gemv_kernel(const float* __restrict__ hidden,
                                                   const float* __restrict__ W) {
    __shared__ float sh_hid[32 * 32];  // [b][oo]

    const int h  = blockIdx.x * 128 + threadIdx.x;
    const int o0 = blockIdx.y * 32;

    // Stage hidden[0..31][o0..o0+31] (1024 elems, 8 per thread)
    #pragma unroll
    for (int k = 0; k < 8; ++k) {
        int idx = threadIdx.x + k * 128;          // 0..1023
        int b   = idx >> 5;
        int oo  = idx & 31;
        sh_hid[idx] = hidden[b * H_DIM + o0 + oo];
    }
    __syncthreads();

    float acc[32];
    #pragma unroll
    for (int b = 0; b < 32; ++b) acc[b] = 0.0f;

    const float* Wp = W + (size_t)o0 * H_DIM + h;
    #pragma unroll
    for (int oo = 0; oo < 32; oo += 8) {
        float w[8];
        #pragma unroll
        for (int j = 0; j < 8; ++j)               // 8 independent LDG (MLP=8)
            w[j] = Wp[(size_t)(oo + j) * H_DIM];
        #pragma unroll
        for (int j = 0; j < 8; ++j) {
            #pragma unroll
            for (int b = 0; b < 32; ++b)
                acc[b] += sh_hid[b * 32 + oo + j] * w[j];
        }
    }

    #pragma unroll
    for (int b = 0; b < 32; ++b)
        atomicAdd(&g_v[b * H_DIM + h], acc[b]);
}

// ---------------------------------------------------------------------------
// Kernel 2: energies[b,s] = dot(enc[s,b,:], v[b,:])
// Grid (S/16, B), block 256 = 8 warps, TWO s-rows per warp.
// v[b] staged in 4 KB smem, each v value loaded once and reused for both rows.
// 16 independent LDG.128 per lane (MLP=16).
// ---------------------------------------------------------------------------
__global__ __launch_bounds__(256) void energy_kernel(const float* __restrict__ enc) {
    __shared__ float4 v_sh[H_DIM / 4];            // 4 KB

    const int b = blockIdx.y;
    v_sh[threadIdx.x] = ((const float4*)(g_v + b * H_DIM))[threadIdx.x];
    __syncthreads();

    const int warp = threadIdx.x >> 5;
    const int lane = threadIdx.x & 31;
    const int s0   = blockIdx.x * 16 + warp * 2;

    const float4* r0 = (const float4*)(enc + ((size_t)s0       * B_DIM + b) * H_DIM);
    const float4* r1 = (const float4*)(enc + ((size_t)(s0 + 1) * B_DIM + b) * H_DIM);

    float a0 = 0.0f, a1 = 0.0f;
    #pragma unroll
    for (int i = 0; i < 8; ++i) {
        float4 e0 = r0[lane + 32 * i];
        float4 e1 = r1[lane + 32 * i];
        float4 v  = v_sh[lane + 32 * i];
        a0 += e0.x * v.x + e0.y * v.y + e0.z * v.z + e0.w * v.w;
        a1 += e1.x * v.x + e1.y * v.y + e1.z * v.z + e1.w * v.w;
    }

    #pragma unroll
    for (int off = 16; off > 0; off >>= 1) {
        a0 += __shfl_xor_sync(0xFFFFFFFFu, a0, off);
        a1 += __shfl_xor_sync(0xFFFFFFFFu, a1, off);
    }

    if (lane == 0) {
        g_e[b * S_DIM + s0]     = a0;
        g_e[b * S_DIM + s0 + 1] = a1;
    }
}

// ---------------------------------------------------------------------------
// Kernel 3: softmax over s per batch; one block (1024 thr) per b, 2 elems/thr.
// ---------------------------------------------------------------------------
__global__ __launch_bounds__(1024) void softmax_kernel(float* __restrict__ out) {
    __shared__ float red[32];

    const int b = blockIdx.x;
    const int t = threadIdx.x;
    const float* e = g_e + b * S_DIM;

    float e0 = e[t];
    float e1 = e[t + 1024];

    float m = fmaxf(e0, e1);
    #pragma unroll
    for (int off = 16; off > 0; off >>= 1)
        m = fmaxf(m, __shfl_xor_sync(0xFFFFFFFFu, m, off));
    if ((t & 31) == 0) red[t >> 5] = m;
    __syncthreads();
    if (t < 32) {
        float v = red[t];
        #pragma unroll
        for (int off = 16; off > 0; off >>= 1)
            v = fmaxf(v, __shfl_xor_sync(0xFFFFFFFFu, v, off));
        red[t] = v;
    }
    __syncthreads();
    m = red[0];
    __syncthreads();

    float x0 = expf(e0 - m);
    float x1 = expf(e1 - m);
    float s = x0 + x1;
    #pragma unroll
    for (int off = 16; off > 0; off >>= 1)
        s += __shfl_xor_sync(0xFFFFFFFFu, s, off);
    if ((t & 31) == 0) red[t >> 5] = s;
    __syncthreads();
    if (t < 32) {
        float v = red[t];
        #pragma unroll
        for (int off = 16; off > 0; off >>= 1)
            v += __shfl_xor_sync(0xFFFFFFFFu, v, off);
        red[t] = v;
    }
    __syncthreads();
    s = red[0];

    float inv = 1.0f / s;
    out[b * S_DIM + t]        = x0 * inv;
    out[b * S_DIM + t + 1024] = x1 * inv;
}

// ---------------------------------------------------------------------------
extern "C" void kernel_launch(void* const* d_in, const int* in_sizes, int n_in,
                              void* d_out, int out_size) {
    const float* hidden = (const float*)d_in[0];
    const float* enc    = (const float*)d_in[1];
    const float* W      = (const float*)d_in[2];
    // d_in[3] = bias: constant per b -> cancels in softmax.

    float* out = (float*)d_out;

    // Zero the v accumulator via a graph-capturable memset node (no kernel).
    void* vptr = nullptr;
    cudaGetSymbolAddress(&vptr, g_v);
    cudaMemsetAsync(vptr, 0, B_DIM * H_DIM * sizeof(float));

    {
        dim3 grid(H_DIM / 128, 32);
        gemv_kernel<<<grid, 128>>>(hidden, W);
    }
    {
        dim3 grid(S_DIM / 16, B_DIM);
        energy_kernel<<<grid, 256>>>(enc);
    }
    softmax_kernel<<<B_DIM, 1024>>>(out);
}